// round 15
// baseline (speedup 1.0000x reference)
#include <cuda_runtime.h>
#include <cuda_bf16.h>
#include <cstdint>

#define NB   8
#define CIN  512
#define COUT 1024
#define PP   2048
#define NH   8
#define DH   128

typedef __nv_bfloat16 bf16;

// ---------------- device scratch (static: no allocation allowed) -------------
__device__ bf16  g_Yb[(size_t)3 * NB * COUT * PP];                   // 96 MB
__device__ float g_ps[(size_t)24 * 8 * 16 * 256];                    // 3 MB partials
__device__ float g_scale[3][COUT];
__device__ float g_shift[3][COUT];
__device__ bf16  g_W[3][COUT * CIN];
__device__ bf16  g_xT[(size_t)NB * PP * CIN];
__device__ bf16  g_Q[(size_t)NB * COUT * PP];
__device__ bf16  g_KT[(size_t)NB * PP * COUT];    // pre-scaled by log2e/sqrt(dh)
__device__ bf16  g_VT[(size_t)NB * PP * COUT];

// ---------------- PTX helpers (baseline PTX only) ----------------------------
__device__ __forceinline__ uint32_t smem_u32(const void* p) {
    uint32_t a;
    asm("{ .reg .u64 t; cvta.to.shared.u64 t, %1; cvt.u32.u64 %0, t; }" : "=r"(a) : "l"(p));
    return a;
}
__device__ __forceinline__ void cp16(uint32_t saddr, const void* g) {
    asm volatile("cp.async.cg.shared.global [%0], [%1], 16;" :: "r"(saddr), "l"(g));
}
#define CP_COMMIT() asm volatile("cp.async.commit_group;" ::: "memory")
template <int N>
__device__ __forceinline__ void cp_wait() {
    asm volatile("cp.async.wait_group %0;" :: "n"(N) : "memory");
}
__device__ __forceinline__ void lma4(uint32_t* r, uint32_t addr) {
    asm volatile("ldmatrix.sync.aligned.m8n8.x4.shared.b16 {%0,%1,%2,%3}, [%4];"
                 : "=r"(r[0]), "=r"(r[1]), "=r"(r[2]), "=r"(r[3]) : "r"(addr));
}
__device__ __forceinline__ void mma16816(float* d, const uint32_t* a, const uint32_t* b) {
    asm volatile("mma.sync.aligned.m16n8k16.row.col.f32.bf16.bf16.f32 "
                 "{%0,%1,%2,%3}, {%4,%5,%6,%7}, {%8,%9}, {%0,%1,%2,%3};"
                 : "+f"(d[0]), "+f"(d[1]), "+f"(d[2]), "+f"(d[3])
                 : "r"(a[0]), "r"(a[1]), "r"(a[2]), "r"(a[3]), "r"(b[0]), "r"(b[1]));
}
__device__ __forceinline__ float ex2f(float x) {
    float y;
    asm("ex2.approx.ftz.f32 %0, %1;" : "=f"(y) : "f"(x));
    return y;
}
__device__ __forceinline__ uint32_t cvt_bf16x2(float hi, float lo) {
    uint32_t r;
    asm("cvt.rn.bf16x2.f32 %0, %1, %2;" : "=r"(r) : "f"(hi), "f"(lo));
    return r;
}

// =============================================================================
// Projection GEMM (single-plane bf16, 1 term) + fused BN partial stats.
// =============================================================================
#define ROWB   80
#define MATB   (128 * ROWB)
#define STAGEB (2 * MATB)
#define OFF_A  0
#define OFF_B  MATB
#define SMEM_BYTES (2 * STAGEB)          // 40960

__global__ __launch_bounds__(256) void proj_gemm(void) {
    extern __shared__ __align__(128) char smem[];
    const uint32_t sb = smem_u32(smem);
    const int tid = threadIdx.x;
    const int L = tid & 31;
    const int w = tid >> 5;
    const int wm = w >> 2, wn = w & 3;
    const int z = blockIdx.z;
    const int m0 = blockIdx.y * 128, n0 = blockIdx.x * 128;

    const bf16* Am = g_W[z >> 3];
    const bf16* Bm = g_xT + (size_t)(z & 7) * PP * CIN;
    bf16* C = g_Yb + (size_t)z * COUT * PP;

    const int ck0 = tid * 2, ck1 = tid * 2 + 1;
    const int lr0 = ck0 >> 2, lc0 = ck0 & 3;
    const int lr1 = ck1 >> 2, lc1 = ck1 & 3;

    const bf16* pA0 = Am + (size_t)(m0 + lr0) * CIN + lc0 * 8;
    const bf16* pA1 = Am + (size_t)(m0 + lr1) * CIN + lc1 * 8;
    const bf16* pB0 = Bm + (size_t)(n0 + lr0) * CIN + lc0 * 8;
    const bf16* pB1 = Bm + (size_t)(n0 + lr1) * CIN + lc1 * 8;
    const uint32_t so0 = lr0 * ROWB + lc0 * 16;
    const uint32_t so1 = lr1 * ROWB + lc1 * 16;

    float acc[4][4][4];
#pragma unroll
    for (int mt = 0; mt < 4; mt++)
#pragma unroll
        for (int nt = 0; nt < 4; nt++)
#pragma unroll
            for (int i = 0; i < 4; i++) acc[mt][nt][i] = 0.0f;

    const int nch = CIN >> 5;
    {
        uint32_t base = sb;
        cp16(base + OFF_A + so0, pA0); cp16(base + OFF_A + so1, pA1);
        cp16(base + OFF_B + so0, pB0); cp16(base + OFF_B + so1, pB1);
        CP_COMMIT();
    }

    const uint32_t a_row = (uint32_t)(wm * 64 + ((L >> 3) & 1) * 8 + (L & 7));
    const uint32_t a_cc  = (uint32_t)(L >> 4);
    const uint32_t b_row = (uint32_t)(wn * 32 + ((L >> 4) << 3) + (L & 7));
    const uint32_t b_cc  = (uint32_t)((L >> 3) & 1);

    for (int ch = 0; ch < nch; ch++) {
        if (ch + 1 < nch) {
            uint32_t base = sb + ((ch + 1) & 1) * STAGEB;
            int kc = (ch + 1) * 32;
            cp16(base + OFF_A + so0, pA0 + kc); cp16(base + OFF_A + so1, pA1 + kc);
            cp16(base + OFF_B + so0, pB0 + kc); cp16(base + OFF_B + so1, pB1 + kc);
            CP_COMMIT();
            cp_wait<1>();
        } else {
            cp_wait<0>();
        }
        __syncthreads();

        uint32_t base = sb + (ch & 1) * STAGEB;
#pragma unroll
        for (int ks = 0; ks < 2; ks++) {
            uint32_t af[4][4], bf[4][2];
            uint32_t acol = (a_cc + ks * 2) * 16;
            uint32_t bcol = (b_cc + ks * 2) * 16;
#pragma unroll
            for (int mt = 0; mt < 4; mt++)
                lma4(af[mt], base + OFF_A + (a_row + mt * 16) * ROWB + acol);
#pragma unroll
            for (int np = 0; np < 2; np++) {
                uint32_t t4[4];
                lma4(t4, base + OFF_B + (b_row + np * 16) * ROWB + bcol);
                bf[2 * np][0] = t4[0]; bf[2 * np][1] = t4[1];
                bf[2 * np + 1][0] = t4[2]; bf[2 * np + 1][1] = t4[3];
            }
#pragma unroll
            for (int mt = 0; mt < 4; mt++)
#pragma unroll
                for (int nt = 0; nt < 4; nt++)
                    mma16816(acc[mt][nt], af[mt], bf[nt]);
        }
        __syncthreads();
    }

    const int tg = L >> 2, tp = L & 3;
#pragma unroll
    for (int mt = 0; mt < 4; mt++) {
        int r0 = m0 + wm * 64 + mt * 16 + tg;
#pragma unroll
        for (int nt = 0; nt < 4; nt++) {
            int c = n0 + wn * 32 + nt * 8 + tp * 2;
            *(uint32_t*)&C[(size_t)r0 * PP + c]       = cvt_bf16x2(acc[mt][nt][1], acc[mt][nt][0]);
            *(uint32_t*)&C[(size_t)(r0 + 8) * PP + c] = cvt_bf16x2(acc[mt][nt][3], acc[mt][nt][2]);
        }
    }

    float* sp = (float*)smem;
#pragma unroll
    for (int mt = 0; mt < 4; mt++) {
#pragma unroll
        for (int half = 0; half < 2; half++) {
            float s = 0.0f, q = 0.0f;
#pragma unroll
            for (int nt = 0; nt < 4; nt++) {
                float a = acc[mt][nt][2 * half], bq = acc[mt][nt][2 * half + 1];
                s += a + bq;
                q += a * a + bq * bq;
            }
            s += __shfl_xor_sync(0xffffffffu, s, 1);
            s += __shfl_xor_sync(0xffffffffu, s, 2);
            q += __shfl_xor_sync(0xffffffffu, q, 1);
            q += __shfl_xor_sync(0xffffffffu, q, 2);
            if (tp == 0) {
                int r = wm * 64 + mt * 16 + tg + 8 * half;
                sp[(wn * 128 + r) * 2]     = s;
                sp[(wn * 128 + r) * 2 + 1] = q;
            }
        }
    }
    __syncthreads();
    if (tid < 128) {
        float s = sp[tid * 2]             + sp[(128 + tid) * 2]
                + sp[(256 + tid) * 2]     + sp[(384 + tid) * 2];
        float q = sp[tid * 2 + 1]         + sp[(128 + tid) * 2 + 1]
                + sp[(256 + tid) * 2 + 1] + sp[(384 + tid) * 2 + 1];
        size_t o = (((size_t)z * 8 + blockIdx.y) * 16 + blockIdx.x) * 256 + tid * 2;
        g_ps[o] = s;
        g_ps[o + 1] = q;
    }
}

// ---------------- stats finalize ---------------------------------------------
__global__ __launch_bounds__(32) void stats_reduce(const float* __restrict__ gq,
                                                   const float* __restrict__ bq,
                                                   const float* __restrict__ gk,
                                                   const float* __restrict__ bk,
                                                   const float* __restrict__ gv,
                                                   const float* __restrict__ bv) {
    int proj = blockIdx.x >> 10;
    int chn  = blockIdx.x & 1023;
    int my   = chn >> 7, row = chn & 127;
    float s = 0.0f, q = 0.0f;
    for (int i = threadIdx.x; i < 128; i += 32) {
        int b = i >> 4, nx = i & 15;
        size_t o = (((size_t)(proj * 8 + b) * 8 + my) * 16 + nx) * 256 + row * 2;
        s += g_ps[o]; q += g_ps[o + 1];
    }
#pragma unroll
    for (int o = 16; o; o >>= 1) {
        s += __shfl_xor_sync(0xffffffffu, s, o);
        q += __shfl_xor_sync(0xffffffffu, q, o);
    }
    if (threadIdx.x == 0) {
        const float inv_n = 1.0f / (float)(NB * PP);
        float mean = s * inv_n;
        float var  = q * inv_n - mean * mean;
        const float* g  = (proj == 0) ? gq : ((proj == 1) ? gk : gv);
        const float* bb = (proj == 0) ? bq : ((proj == 1) ? bk : bv);
        float sc = g[chn] * rsqrtf(var + 1e-5f);
        float sh = bb[chn] - mean * sc;
        if (proj == 1) {
            const float cS = 1.4426950408889634f * 0.08838834764831845f;
            sc *= cS; sh *= cS;
        }
        g_scale[proj][chn] = sc;
        g_shift[proj][chn] = sh;
    }
}

// =============================================================================
// Fused flash attention — R12 known-good: 512 threads (16 warps),
// maxless softmax, SMEM P, double-buffered V/Q.
// =============================================================================
#define APITCH 272
#define TILEB  (128 * APITCH)
#define SM_K   0
#define SM_V0  (1 * TILEB)
#define SM_V1  (2 * TILEB)
#define SM_Q0  (3 * TILEB)
#define SM_Q1  (4 * TILEB)
#define SM_P   (5 * TILEB)
#define SM_RS  (6 * TILEB)
#define SMEM_ATTN (SM_RS + 2048)         // 210944

__device__ __forceinline__ void load_plane512(uint32_t sb, uint32_t off,
                                              const bf16* __restrict__ src,
                                              size_t stride, int tid) {
#pragma unroll
    for (int i = 0; i < 4; i++) {
        int idx = tid + i * 512;
        int r = idx >> 4, cc = idx & 15;
        cp16(sb + off + r * APITCH + cc * 16, src + (size_t)r * stride + cc * 8);
    }
}

__global__ __launch_bounds__(512, 1) void attn_fused(float* __restrict__ out) {
    extern __shared__ __align__(128) char smem[];
    const uint32_t sb = smem_u32(smem);
    const int tid = threadIdx.x;
    const int L = tid & 31, w = tid >> 5;
    const int wm = w >> 2, wn = w & 3;
    const int tg = L >> 2, tp = L & 3;
    const int it = blockIdx.x;
    const int z = blockIdx.y, b = z >> 3, h = z & 7;

    const bf16* Kp = g_KT + ((size_t)b * PP + it * 128) * COUT + h * DH;
    const bf16* Vp = g_VT + (size_t)b * PP * COUT + h * DH;
    const bf16* Qp = g_Q + ((size_t)b * COUT + h * DH) * PP;

    load_plane512(sb, SM_K, Kp, COUT, tid);
    load_plane512(sb, SM_V0, Vp, COUT, tid);
    CP_COMMIT();
    load_plane512(sb, SM_Q0, Qp, PP, tid);
    CP_COMMIT();

    const uint32_t a_row = (uint32_t)(wm * 32 + ((L >> 3) & 1) * 8 + (L & 7));
    const uint32_t a_cc  = (uint32_t)(L >> 4);
    const uint32_t b_row = (uint32_t)(wn * 32 + ((L >> 4) << 3) + (L & 7));
    const uint32_t b_cc  = (uint32_t)((L >> 3) & 1);

    float oacc[2][4][4];
    float lrow[2][2];
#pragma unroll
    for (int mt = 0; mt < 2; mt++) {
        lrow[mt][0] = lrow[mt][1] = 0.0f;
#pragma unroll
        for (int nt = 0; nt < 4; nt++)
#pragma unroll
            for (int i = 0; i < 4; i++) oacc[mt][nt][i] = 0.0f;
    }

    for (int jt = 0; jt < 16; jt++) {
        const uint32_t vbase = sb + SM_V0 + (uint32_t)(jt & 1) * TILEB;
        const uint32_t qbase = sb + SM_Q0 + (uint32_t)(jt & 1) * TILEB;

        cp_wait<1>();
        __syncthreads();

        if (jt + 1 < 16) {
            load_plane512(sb, SM_V0 + (uint32_t)((jt + 1) & 1) * TILEB,
                          Vp + (size_t)(jt + 1) * 128 * COUT, COUT, tid);
            CP_COMMIT();
        }

        float sacc[2][4][4];
#pragma unroll
        for (int mt = 0; mt < 2; mt++)
#pragma unroll
            for (int nt = 0; nt < 4; nt++)
#pragma unroll
                for (int i = 0; i < 4; i++) sacc[mt][nt][i] = 0.0f;

#pragma unroll
        for (int ks = 0; ks < 8; ks++) {
            uint32_t af[2][4], bf[4][2];
            uint32_t acol = (a_cc + ks * 2) * 16;
            uint32_t bcol = (b_cc + ks * 2) * 16;
#pragma unroll
            for (int mt = 0; mt < 2; mt++)
                lma4(af[mt], sb + SM_K + (a_row + mt * 16) * APITCH + acol);
#pragma unroll
            for (int np = 0; np < 2; np++) {
                uint32_t t4[4];
                lma4(t4, vbase + (b_row + np * 16) * APITCH + bcol);
                bf[2 * np][0] = t4[0]; bf[2 * np][1] = t4[1];
                bf[2 * np + 1][0] = t4[2]; bf[2 * np + 1][1] = t4[3];
            }
#pragma unroll
            for (int mt = 0; mt < 2; mt++)
#pragma unroll
                for (int nt = 0; nt < 4; nt++)
                    mma16816(sacc[mt][nt], af[mt], bf[nt]);
        }

#pragma unroll
        for (int mt = 0; mt < 2; mt++) {
#pragma unroll
            for (int half = 0; half < 2; half++) {
                int r = wm * 32 + mt * 16 + tg + half * 8;
                float rs = 0.0f;
#pragma unroll
                for (int nt = 0; nt < 4; nt++) {
                    float p0 = ex2f(sacc[mt][nt][2 * half]);
                    float p1 = ex2f(sacc[mt][nt][2 * half + 1]);
                    rs += p0 + p1;
                    uint32_t col = wn * 32 + nt * 8 + 2 * tp;
                    *(uint32_t*)(smem + SM_P + r * APITCH + col * 2) = cvt_bf16x2(p1, p0);
                }
                lrow[mt][half] += rs;
            }
        }

        if (jt + 1 < 16) cp_wait<1>(); else cp_wait<0>();
        __syncthreads();

        if (jt + 1 < 16) {
            load_plane512(sb, SM_Q0 + (uint32_t)((jt + 1) & 1) * TILEB,
                          Qp + (size_t)(jt + 1) * 128, PP, tid);
            CP_COMMIT();
        }

#pragma unroll
        for (int ks = 0; ks < 8; ks++) {
            uint32_t af[2][4], bf[4][2];
            uint32_t acol = (a_cc + ks * 2) * 16;
            uint32_t bcol = (b_cc + ks * 2) * 16;
#pragma unroll
            for (int mt = 0; mt < 2; mt++)
                lma4(af[mt], sb + SM_P + (a_row + mt * 16) * APITCH + acol);
#pragma unroll
            for (int np = 0; np < 2; np++) {
                uint32_t t4[4];
                lma4(t4, qbase + (b_row + np * 16) * APITCH + bcol);
                bf[2 * np][0] = t4[0]; bf[2 * np][1] = t4[1];
                bf[2 * np + 1][0] = t4[2]; bf[2 * np + 1][1] = t4[3];
            }
#pragma unroll
            for (int mt = 0; mt < 2; mt++)
#pragma unroll
                for (int nt = 0; nt < 4; nt++)
                    mma16816(oacc[mt][nt], af[mt], bf[nt]);
        }
        __syncthreads();
    }

#pragma unroll
    for (int mt = 0; mt < 2; mt++) {
#pragma unroll
        for (int half = 0; half < 2; half++) {
            float l = lrow[mt][half];
            l += __shfl_xor_sync(0xffffffffu, l, 1);
            l += __shfl_xor_sync(0xffffffffu, l, 2);
            if (tp == 0) {
                int r = wm * 32 + mt * 16 + tg + half * 8;
                *(float*)(smem + SM_RS + (wn * 128 + r) * 4) = l;
            }
        }
    }
    __syncthreads();
#pragma unroll
    for (int mt = 0; mt < 2; mt++) {
#pragma unroll
        for (int half = 0; half < 2; half++) {
            int r = wm * 32 + mt * 16 + tg + half * 8;
            lrow[mt][half] = *(float*)(smem + SM_RS + r * 4)
                           + *(float*)(smem + SM_RS + (128 + r) * 4)
                           + *(float*)(smem + SM_RS + (256 + r) * 4)
                           + *(float*)(smem + SM_RS + (384 + r) * 4);
        }
    }
    __syncthreads();

    float* fbuf = (float*)smem;
#pragma unroll
    for (int mt = 0; mt < 2; mt++) {
#pragma unroll
        for (int half = 0; half < 2; half++) {
            int r = wm * 32 + mt * 16 + tg + half * 8;
            float inv = 1.0f / lrow[mt][half];
#pragma unroll
            for (int nt = 0; nt < 4; nt++) {
                int c = wn * 32 + nt * 8 + 2 * tp;
                fbuf[(size_t)c * 132 + r]       = oacc[mt][nt][2 * half] * inv;
                fbuf[(size_t)(c + 1) * 132 + r] = oacc[mt][nt][2 * half + 1] * inv;
            }
        }
    }
    __syncthreads();
    const size_t obase = ((size_t)b * COUT + h * DH) * PP + (size_t)it * 128;
#pragma unroll
    for (int rr = 0; rr < 8; rr++) {
        int r = w * 8 + rr;
        float4 v = *(float4*)&fbuf[(size_t)r * 132 + L * 4];
        *(float4*)&out[obase + (size_t)r * PP + L * 4] = v;
    }
}

// ---------------- conversions ------------------------------------------------
__global__ __launch_bounds__(256) void convert_w(const float* __restrict__ Wq,
                                                 const float* __restrict__ Wk,
                                                 const float* __restrict__ Wv) {
    int proj = blockIdx.z;
    const float* W = (proj == 0) ? Wq : ((proj == 1) ? Wk : Wv);
    size_t e = ((size_t)blockIdx.x * 256 + threadIdx.x) * 4;
    float4 v = *(const float4*)(W + e);
    ((uint32_t*)&g_W[proj][e])[0] = cvt_bf16x2(v.y, v.x);
    ((uint32_t*)&g_W[proj][e])[1] = cvt_bf16x2(v.w, v.z);
}

// ---------------- transpose x: [c][p] -> [p][c], packed bf16x2 stores --------
__global__ __launch_bounds__(256) void transpose_x(const float* __restrict__ x) {
    __shared__ float t[32][33];
    int b = blockIdx.z;
    int p0 = blockIdx.x * 32, c0 = blockIdx.y * 32;
    int tx = threadIdx.x & 31, ty = threadIdx.x >> 5;   // 32 x 8
#pragma unroll
    for (int j = 0; j < 4; j++)
        t[ty + 8 * j][tx] = x[((size_t)b * CIN + c0 + ty + 8 * j) * PP + p0 + tx];
    __syncthreads();
    // store phase: thread -> (p, channel-pair); 32-bit coalesced stores
    int cp = threadIdx.x & 15, pl = threadIdx.x >> 4;   // cp 0..15, pl 0..15
#pragma unroll
    for (int i = 0; i < 2; i++) {
        int p = pl + 16 * i;
        float v0 = t[2 * cp][p];
        float v1 = t[2 * cp + 1][p];
        *(uint32_t*)&g_xT[((size_t)b * PP + p0 + p) * CIN + c0 + 2 * cp] =
            cvt_bf16x2(v1, v0);
    }
}

// ---------------- BN apply: Q path -------------------------------------------
__global__ __launch_bounds__(256) void bn_apply_q(void) {
    size_t e = ((size_t)blockIdx.x * 256 + threadIdx.x) * 8;
    int ch = (int)((e >> 11) & (COUT - 1));
    float sc = g_scale[0][ch], sh = g_shift[0][ch];
    uint4 raw = *(uint4*)&g_Yb[e];
    uint32_t rw[4] = {raw.x, raw.y, raw.z, raw.w};
    uint32_t outp[4];
#pragma unroll
    for (int i = 0; i < 4; i++) {
        __nv_bfloat162 pv = *(__nv_bfloat162*)&rw[i];
        float a = __bfloat162float(__low2bfloat16(pv));
        float c = __bfloat162float(__high2bfloat16(pv));
        a = sc * a + sh; a = (a < 0.0f) ? 0.1f * a : a;
        c = sc * c + sh; c = (c < 0.0f) ? 0.1f * c : c;
        outp[i] = cvt_bf16x2(c, a);
    }
    *(uint4*)&g_Q[e] = make_uint4(outp[0], outp[1], outp[2], outp[3]);
}

// ---------------- BN apply + transpose: K/V, packed bf16x2 stores ------------
__global__ __launch_bounds__(256) void bn_apply_t(void) {
    __shared__ float t[32][33];
    int z = blockIdx.z;
    int proj = 1 + (z >> 3), b = z & 7;
    int p0 = blockIdx.x * 32, c0 = blockIdx.y * 32;
    int tx = threadIdx.x & 31, ty = threadIdx.x >> 5;
#pragma unroll
    for (int j = 0; j < 4; j++) {
        int c = c0 + ty + 8 * j;
        float sc = g_scale[proj][c], sh = g_shift[proj][c];
        float v = __bfloat162float(
            g_Yb[(((size_t)proj * NB + b) * COUT + c) * PP + p0 + tx]);
        v = sc * v + sh;
        v = (v < 0.0f) ? 0.1f * v : v;
        t[ty + 8 * j][tx] = v;
    }
    __syncthreads();
    bf16* T = (proj == 1) ? g_KT : g_VT;
    int cp = threadIdx.x & 15, pl = threadIdx.x >> 4;
#pragma unroll
    for (int i = 0; i < 2; i++) {
        int p = pl + 16 * i;
        float v0 = t[2 * cp][p];
        float v1 = t[2 * cp + 1][p];
        *(uint32_t*)&T[((size_t)b * PP + p0 + p) * COUT + c0 + 2 * cp] =
            cvt_bf16x2(v1, v0);
    }
}

// ---------------- launch -----------------------------------------------------
extern "C" void kernel_launch(void* const* d_in, const int* in_sizes, int n_in,
                              void* d_out, int out_size)
{
    (void)in_sizes; (void)n_in; (void)out_size;
    const float* x  = (const float*)d_in[0];
    const float* Wq = (const float*)d_in[1];
    const float* gq = (const float*)d_in[2];
    const float* bq = (const float*)d_in[3];
    const float* Wk = (const float*)d_in[4];
    const float* gk = (const float*)d_in[5];
    const float* bk = (const float*)d_in[6];
    const float* Wv = (const float*)d_in[7];
    const float* gv = (const float*)d_in[8];
    const float* bv = (const float*)d_in[9];
    float* out = (float*)d_out;

    cudaFuncSetAttribute(proj_gemm,  cudaFuncAttributeMaxDynamicSharedMemorySize, SMEM_BYTES);
    cudaFuncSetAttribute(attn_fused, cudaFuncAttributeMaxDynamicSharedMemorySize, SMEM_ATTN);

    // 1) input conversions
    convert_w<<<dim3(COUT * CIN / 4 / 256, 1, 3), 256>>>(Wq, Wk, Wv);
    transpose_x<<<dim3(PP / 32, CIN / 32, NB), 256>>>(x);
    // 2) Y = W x (bf16), fused BN partial stats
    proj_gemm<<<dim3(PP / 128, COUT / 128, 24), 256, SMEM_BYTES>>>();
    // 3) finalize BN stats (cS folded into K)
    stats_reduce<<<3 * COUT, 32>>>(gq, bq, gk, bk, gv, bv);
    // 4) BN + LeakyReLU, emit Q / K^T / V^T single bf16 (packed stores)
    bn_apply_q<<<(unsigned)((size_t)NB * COUT * PP / 8 / 256), 256>>>();
    bn_apply_t<<<dim3(PP / 32, COUT / 32, 16), 256>>>();
    // 5) fused attention (R12 known-good: 512 threads, SMEM P, dbuf V/Q)
    attn_fused<<<dim3(16, 64), 512, SMEM_ATTN>>>(out);
}

// round 16
// speedup vs baseline: 1.5152x; 1.5152x over previous
#include <cuda_runtime.h>
#include <cuda_bf16.h>
#include <cstdint>

#define NB   8
#define CIN  512
#define COUT 1024
#define PP   2048
#define NH   8
#define DH   128

typedef __nv_bfloat16 bf16;

// ---------------- device scratch (static: no allocation allowed) -------------
__device__ bf16  g_Yb[(size_t)3 * NB * COUT * PP];                   // 96 MB
__device__ float g_ps[(size_t)24 * 8 * 16 * 256];                    // 3 MB partials
__device__ float g_scale[3][COUT];
__device__ float g_shift[3][COUT];
__device__ bf16  g_W[3][COUT * CIN];
__device__ bf16  g_xT[(size_t)NB * PP * CIN];
__device__ bf16  g_Q[(size_t)NB * COUT * PP];
__device__ bf16  g_KT[(size_t)NB * PP * COUT];    // pre-scaled by log2e/sqrt(dh)
__device__ bf16  g_VT[(size_t)NB * PP * COUT];

// ---------------- PTX helpers (baseline PTX only) ----------------------------
__device__ __forceinline__ uint32_t smem_u32(const void* p) {
    uint32_t a;
    asm("{ .reg .u64 t; cvta.to.shared.u64 t, %1; cvt.u32.u64 %0, t; }" : "=r"(a) : "l"(p));
    return a;
}
__device__ __forceinline__ void cp16(uint32_t saddr, const void* g) {
    asm volatile("cp.async.cg.shared.global [%0], [%1], 16;" :: "r"(saddr), "l"(g));
}
#define CP_COMMIT() asm volatile("cp.async.commit_group;" ::: "memory")
template <int N>
__device__ __forceinline__ void cp_wait() {
    asm volatile("cp.async.wait_group %0;" :: "n"(N) : "memory");
}
__device__ __forceinline__ void lma4(uint32_t* r, uint32_t addr) {
    asm volatile("ldmatrix.sync.aligned.m8n8.x4.shared.b16 {%0,%1,%2,%3}, [%4];"
                 : "=r"(r[0]), "=r"(r[1]), "=r"(r[2]), "=r"(r[3]) : "r"(addr));
}
__device__ __forceinline__ void mma16816(float* d, const uint32_t* a, const uint32_t* b) {
    asm volatile("mma.sync.aligned.m16n8k16.row.col.f32.bf16.bf16.f32 "
                 "{%0,%1,%2,%3}, {%4,%5,%6,%7}, {%8,%9}, {%0,%1,%2,%3};"
                 : "+f"(d[0]), "+f"(d[1]), "+f"(d[2]), "+f"(d[3])
                 : "r"(a[0]), "r"(a[1]), "r"(a[2]), "r"(a[3]), "r"(b[0]), "r"(b[1]));
}
__device__ __forceinline__ float ex2f(float x) {
    float y;
    asm("ex2.approx.ftz.f32 %0, %1;" : "=f"(y) : "f"(x));
    return y;
}
__device__ __forceinline__ uint32_t cvt_bf16x2(float hi, float lo) {
    uint32_t r;
    asm("cvt.rn.bf16x2.f32 %0, %1, %2;" : "=r"(r) : "f"(hi), "f"(lo));
    return r;
}

// =============================================================================
// Projection GEMM (single-plane bf16, 1 term) + fused BN partial stats.
// =============================================================================
#define ROWB   80
#define MATB   (128 * ROWB)
#define STAGEB (2 * MATB)
#define OFF_A  0
#define OFF_B  MATB
#define SMEM_BYTES (2 * STAGEB)          // 40960

__global__ __launch_bounds__(256) void proj_gemm(void) {
    extern __shared__ __align__(128) char smem[];
    const uint32_t sb = smem_u32(smem);
    const int tid = threadIdx.x;
    const int L = tid & 31;
    const int w = tid >> 5;
    const int wm = w >> 2, wn = w & 3;
    const int z = blockIdx.z;
    const int m0 = blockIdx.y * 128, n0 = blockIdx.x * 128;

    const bf16* Am = g_W[z >> 3];
    const bf16* Bm = g_xT + (size_t)(z & 7) * PP * CIN;
    bf16* C = g_Yb + (size_t)z * COUT * PP;

    const int ck0 = tid * 2, ck1 = tid * 2 + 1;
    const int lr0 = ck0 >> 2, lc0 = ck0 & 3;
    const int lr1 = ck1 >> 2, lc1 = ck1 & 3;

    const bf16* pA0 = Am + (size_t)(m0 + lr0) * CIN + lc0 * 8;
    const bf16* pA1 = Am + (size_t)(m0 + lr1) * CIN + lc1 * 8;
    const bf16* pB0 = Bm + (size_t)(n0 + lr0) * CIN + lc0 * 8;
    const bf16* pB1 = Bm + (size_t)(n0 + lr1) * CIN + lc1 * 8;
    const uint32_t so0 = lr0 * ROWB + lc0 * 16;
    const uint32_t so1 = lr1 * ROWB + lc1 * 16;

    float acc[4][4][4];
#pragma unroll
    for (int mt = 0; mt < 4; mt++)
#pragma unroll
        for (int nt = 0; nt < 4; nt++)
#pragma unroll
            for (int i = 0; i < 4; i++) acc[mt][nt][i] = 0.0f;

    const int nch = CIN >> 5;
    {
        uint32_t base = sb;
        cp16(base + OFF_A + so0, pA0); cp16(base + OFF_A + so1, pA1);
        cp16(base + OFF_B + so0, pB0); cp16(base + OFF_B + so1, pB1);
        CP_COMMIT();
    }

    const uint32_t a_row = (uint32_t)(wm * 64 + ((L >> 3) & 1) * 8 + (L & 7));
    const uint32_t a_cc  = (uint32_t)(L >> 4);
    const uint32_t b_row = (uint32_t)(wn * 32 + ((L >> 4) << 3) + (L & 7));
    const uint32_t b_cc  = (uint32_t)((L >> 3) & 1);

    for (int ch = 0; ch < nch; ch++) {
        if (ch + 1 < nch) {
            uint32_t base = sb + ((ch + 1) & 1) * STAGEB;
            int kc = (ch + 1) * 32;
            cp16(base + OFF_A + so0, pA0 + kc); cp16(base + OFF_A + so1, pA1 + kc);
            cp16(base + OFF_B + so0, pB0 + kc); cp16(base + OFF_B + so1, pB1 + kc);
            CP_COMMIT();
            cp_wait<1>();
        } else {
            cp_wait<0>();
        }
        __syncthreads();

        uint32_t base = sb + (ch & 1) * STAGEB;
#pragma unroll
        for (int ks = 0; ks < 2; ks++) {
            uint32_t af[4][4], bf[4][2];
            uint32_t acol = (a_cc + ks * 2) * 16;
            uint32_t bcol = (b_cc + ks * 2) * 16;
#pragma unroll
            for (int mt = 0; mt < 4; mt++)
                lma4(af[mt], base + OFF_A + (a_row + mt * 16) * ROWB + acol);
#pragma unroll
            for (int np = 0; np < 2; np++) {
                uint32_t t4[4];
                lma4(t4, base + OFF_B + (b_row + np * 16) * ROWB + bcol);
                bf[2 * np][0] = t4[0]; bf[2 * np][1] = t4[1];
                bf[2 * np + 1][0] = t4[2]; bf[2 * np + 1][1] = t4[3];
            }
#pragma unroll
            for (int mt = 0; mt < 4; mt++)
#pragma unroll
                for (int nt = 0; nt < 4; nt++)
                    mma16816(acc[mt][nt], af[mt], bf[nt]);
        }
        __syncthreads();
    }

    const int tg = L >> 2, tp = L & 3;
#pragma unroll
    for (int mt = 0; mt < 4; mt++) {
        int r0 = m0 + wm * 64 + mt * 16 + tg;
#pragma unroll
        for (int nt = 0; nt < 4; nt++) {
            int c = n0 + wn * 32 + nt * 8 + tp * 2;
            *(uint32_t*)&C[(size_t)r0 * PP + c]       = cvt_bf16x2(acc[mt][nt][1], acc[mt][nt][0]);
            *(uint32_t*)&C[(size_t)(r0 + 8) * PP + c] = cvt_bf16x2(acc[mt][nt][3], acc[mt][nt][2]);
        }
    }

    float* sp = (float*)smem;
#pragma unroll
    for (int mt = 0; mt < 4; mt++) {
#pragma unroll
        for (int half = 0; half < 2; half++) {
            float s = 0.0f, q = 0.0f;
#pragma unroll
            for (int nt = 0; nt < 4; nt++) {
                float a = acc[mt][nt][2 * half], bq = acc[mt][nt][2 * half + 1];
                s += a + bq;
                q += a * a + bq * bq;
            }
            s += __shfl_xor_sync(0xffffffffu, s, 1);
            s += __shfl_xor_sync(0xffffffffu, s, 2);
            q += __shfl_xor_sync(0xffffffffu, q, 1);
            q += __shfl_xor_sync(0xffffffffu, q, 2);
            if (tp == 0) {
                int r = wm * 64 + mt * 16 + tg + 8 * half;
                sp[(wn * 128 + r) * 2]     = s;
                sp[(wn * 128 + r) * 2 + 1] = q;
            }
        }
    }
    __syncthreads();
    if (tid < 128) {
        float s = sp[tid * 2]             + sp[(128 + tid) * 2]
                + sp[(256 + tid) * 2]     + sp[(384 + tid) * 2];
        float q = sp[tid * 2 + 1]         + sp[(128 + tid) * 2 + 1]
                + sp[(256 + tid) * 2 + 1] + sp[(384 + tid) * 2 + 1];
        size_t o = (((size_t)z * 8 + blockIdx.y) * 16 + blockIdx.x) * 256 + tid * 2;
        g_ps[o] = s;
        g_ps[o + 1] = q;
    }
}

// ---------------- stats finalize ---------------------------------------------
__global__ __launch_bounds__(32) void stats_reduce(const float* __restrict__ gq,
                                                   const float* __restrict__ bq,
                                                   const float* __restrict__ gk,
                                                   const float* __restrict__ bk,
                                                   const float* __restrict__ gv,
                                                   const float* __restrict__ bv) {
    int proj = blockIdx.x >> 10;
    int chn  = blockIdx.x & 1023;
    int my   = chn >> 7, row = chn & 127;
    float s = 0.0f, q = 0.0f;
    for (int i = threadIdx.x; i < 128; i += 32) {
        int b = i >> 4, nx = i & 15;
        size_t o = (((size_t)(proj * 8 + b) * 8 + my) * 16 + nx) * 256 + row * 2;
        s += g_ps[o]; q += g_ps[o + 1];
    }
#pragma unroll
    for (int o = 16; o; o >>= 1) {
        s += __shfl_xor_sync(0xffffffffu, s, o);
        q += __shfl_xor_sync(0xffffffffu, q, o);
    }
    if (threadIdx.x == 0) {
        const float inv_n = 1.0f / (float)(NB * PP);
        float mean = s * inv_n;
        float var  = q * inv_n - mean * mean;
        const float* g  = (proj == 0) ? gq : ((proj == 1) ? gk : gv);
        const float* bb = (proj == 0) ? bq : ((proj == 1) ? bk : bv);
        float sc = g[chn] * rsqrtf(var + 1e-5f);
        float sh = bb[chn] - mean * sc;
        if (proj == 1) {
            const float cS = 1.4426950408889634f * 0.08838834764831845f;
            sc *= cS; sh *= cS;
        }
        g_scale[proj][chn] = sc;
        g_shift[proj][chn] = sh;
    }
}

// =============================================================================
// Fused flash attention — R12 known-good: 512 threads (16 warps),
// maxless softmax, SMEM P, double-buffered V/Q.
// =============================================================================
#define APITCH 272
#define TILEB  (128 * APITCH)
#define SM_K   0
#define SM_V0  (1 * TILEB)
#define SM_V1  (2 * TILEB)
#define SM_Q0  (3 * TILEB)
#define SM_Q1  (4 * TILEB)
#define SM_P   (5 * TILEB)
#define SM_RS  (6 * TILEB)
#define SMEM_ATTN (SM_RS + 2048)         // 210944

__device__ __forceinline__ void load_plane512(uint32_t sb, uint32_t off,
                                              const bf16* __restrict__ src,
                                              size_t stride, int tid) {
#pragma unroll
    for (int i = 0; i < 4; i++) {
        int idx = tid + i * 512;
        int r = idx >> 4, cc = idx & 15;
        cp16(sb + off + r * APITCH + cc * 16, src + (size_t)r * stride + cc * 8);
    }
}

__global__ __launch_bounds__(512, 1) void attn_fused(float* __restrict__ out) {
    extern __shared__ __align__(128) char smem[];
    const uint32_t sb = smem_u32(smem);
    const int tid = threadIdx.x;
    const int L = tid & 31, w = tid >> 5;
    const int wm = w >> 2, wn = w & 3;
    const int tg = L >> 2, tp = L & 3;
    const int it = blockIdx.x;
    const int z = blockIdx.y, b = z >> 3, h = z & 7;

    const bf16* Kp = g_KT + ((size_t)b * PP + it * 128) * COUT + h * DH;
    const bf16* Vp = g_VT + (size_t)b * PP * COUT + h * DH;
    const bf16* Qp = g_Q + ((size_t)b * COUT + h * DH) * PP;

    load_plane512(sb, SM_K, Kp, COUT, tid);
    load_plane512(sb, SM_V0, Vp, COUT, tid);
    CP_COMMIT();
    load_plane512(sb, SM_Q0, Qp, PP, tid);
    CP_COMMIT();

    const uint32_t a_row = (uint32_t)(wm * 32 + ((L >> 3) & 1) * 8 + (L & 7));
    const uint32_t a_cc  = (uint32_t)(L >> 4);
    const uint32_t b_row = (uint32_t)(wn * 32 + ((L >> 4) << 3) + (L & 7));
    const uint32_t b_cc  = (uint32_t)((L >> 3) & 1);

    float oacc[2][4][4];
    float lrow[2][2];
#pragma unroll
    for (int mt = 0; mt < 2; mt++) {
        lrow[mt][0] = lrow[mt][1] = 0.0f;
#pragma unroll
        for (int nt = 0; nt < 4; nt++)
#pragma unroll
            for (int i = 0; i < 4; i++) oacc[mt][nt][i] = 0.0f;
    }

    for (int jt = 0; jt < 16; jt++) {
        const uint32_t vbase = sb + SM_V0 + (uint32_t)(jt & 1) * TILEB;
        const uint32_t qbase = sb + SM_Q0 + (uint32_t)(jt & 1) * TILEB;

        cp_wait<1>();
        __syncthreads();

        if (jt + 1 < 16) {
            load_plane512(sb, SM_V0 + (uint32_t)((jt + 1) & 1) * TILEB,
                          Vp + (size_t)(jt + 1) * 128 * COUT, COUT, tid);
            CP_COMMIT();
        }

        float sacc[2][4][4];
#pragma unroll
        for (int mt = 0; mt < 2; mt++)
#pragma unroll
            for (int nt = 0; nt < 4; nt++)
#pragma unroll
                for (int i = 0; i < 4; i++) sacc[mt][nt][i] = 0.0f;

#pragma unroll
        for (int ks = 0; ks < 8; ks++) {
            uint32_t af[2][4], bf[4][2];
            uint32_t acol = (a_cc + ks * 2) * 16;
            uint32_t bcol = (b_cc + ks * 2) * 16;
#pragma unroll
            for (int mt = 0; mt < 2; mt++)
                lma4(af[mt], sb + SM_K + (a_row + mt * 16) * APITCH + acol);
#pragma unroll
            for (int np = 0; np < 2; np++) {
                uint32_t t4[4];
                lma4(t4, vbase + (b_row + np * 16) * APITCH + bcol);
                bf[2 * np][0] = t4[0]; bf[2 * np][1] = t4[1];
                bf[2 * np + 1][0] = t4[2]; bf[2 * np + 1][1] = t4[3];
            }
#pragma unroll
            for (int mt = 0; mt < 2; mt++)
#pragma unroll
                for (int nt = 0; nt < 4; nt++)
                    mma16816(sacc[mt][nt], af[mt], bf[nt]);
        }

#pragma unroll
        for (int mt = 0; mt < 2; mt++) {
#pragma unroll
            for (int half = 0; half < 2; half++) {
                int r = wm * 32 + mt * 16 + tg + half * 8;
                float rs = 0.0f;
#pragma unroll
                for (int nt = 0; nt < 4; nt++) {
                    float p0 = ex2f(sacc[mt][nt][2 * half]);
                    float p1 = ex2f(sacc[mt][nt][2 * half + 1]);
                    rs += p0 + p1;
                    uint32_t col = wn * 32 + nt * 8 + 2 * tp;
                    *(uint32_t*)(smem + SM_P + r * APITCH + col * 2) = cvt_bf16x2(p1, p0);
                }
                lrow[mt][half] += rs;
            }
        }

        if (jt + 1 < 16) cp_wait<1>(); else cp_wait<0>();
        __syncthreads();

        if (jt + 1 < 16) {
            load_plane512(sb, SM_Q0 + (uint32_t)((jt + 1) & 1) * TILEB,
                          Qp + (size_t)(jt + 1) * 128, PP, tid);
            CP_COMMIT();
        }

#pragma unroll
        for (int ks = 0; ks < 8; ks++) {
            uint32_t af[2][4], bf[4][2];
            uint32_t acol = (a_cc + ks * 2) * 16;
            uint32_t bcol = (b_cc + ks * 2) * 16;
#pragma unroll
            for (int mt = 0; mt < 2; mt++)
                lma4(af[mt], sb + SM_P + (a_row + mt * 16) * APITCH + acol);
#pragma unroll
            for (int np = 0; np < 2; np++) {
                uint32_t t4[4];
                lma4(t4, qbase + (b_row + np * 16) * APITCH + bcol);
                bf[2 * np][0] = t4[0]; bf[2 * np][1] = t4[1];
                bf[2 * np + 1][0] = t4[2]; bf[2 * np + 1][1] = t4[3];
            }
#pragma unroll
            for (int mt = 0; mt < 2; mt++)
#pragma unroll
                for (int nt = 0; nt < 4; nt++)
                    mma16816(oacc[mt][nt], af[mt], bf[nt]);
        }
        __syncthreads();
    }

#pragma unroll
    for (int mt = 0; mt < 2; mt++) {
#pragma unroll
        for (int half = 0; half < 2; half++) {
            float l = lrow[mt][half];
            l += __shfl_xor_sync(0xffffffffu, l, 1);
            l += __shfl_xor_sync(0xffffffffu, l, 2);
            if (tp == 0) {
                int r = wm * 32 + mt * 16 + tg + half * 8;
                *(float*)(smem + SM_RS + (wn * 128 + r) * 4) = l;
            }
        }
    }
    __syncthreads();
#pragma unroll
    for (int mt = 0; mt < 2; mt++) {
#pragma unroll
        for (int half = 0; half < 2; half++) {
            int r = wm * 32 + mt * 16 + tg + half * 8;
            lrow[mt][half] = *(float*)(smem + SM_RS + r * 4)
                           + *(float*)(smem + SM_RS + (128 + r) * 4)
                           + *(float*)(smem + SM_RS + (256 + r) * 4)
                           + *(float*)(smem + SM_RS + (384 + r) * 4);
        }
    }
    __syncthreads();

    float* fbuf = (float*)smem;
#pragma unroll
    for (int mt = 0; mt < 2; mt++) {
#pragma unroll
        for (int half = 0; half < 2; half++) {
            int r = wm * 32 + mt * 16 + tg + half * 8;
            float inv = 1.0f / lrow[mt][half];
#pragma unroll
            for (int nt = 0; nt < 4; nt++) {
                int c = wn * 32 + nt * 8 + 2 * tp;
                fbuf[(size_t)c * 132 + r]       = oacc[mt][nt][2 * half] * inv;
                fbuf[(size_t)(c + 1) * 132 + r] = oacc[mt][nt][2 * half + 1] * inv;
            }
        }
    }
    __syncthreads();
    const size_t obase = ((size_t)b * COUT + h * DH) * PP + (size_t)it * 128;
#pragma unroll
    for (int rr = 0; rr < 8; rr++) {
        int r = w * 8 + rr;
        float4 v = *(float4*)&fbuf[(size_t)r * 132 + L * 4];
        *(float4*)&out[obase + (size_t)r * PP + L * 4] = v;
    }
}

// ---------------- conversions ------------------------------------------------
__global__ __launch_bounds__(256) void convert_w(const float* __restrict__ Wq,
                                                 const float* __restrict__ Wk,
                                                 const float* __restrict__ Wv) {
    int proj = blockIdx.z;
    const float* W = (proj == 0) ? Wq : ((proj == 1) ? Wk : Wv);
    size_t e = ((size_t)blockIdx.x * 256 + threadIdx.x) * 4;
    float4 v = *(const float4*)(W + e);
    ((uint32_t*)&g_W[proj][e])[0] = cvt_bf16x2(v.y, v.x);
    ((uint32_t*)&g_W[proj][e])[1] = cvt_bf16x2(v.w, v.z);
}

__global__ __launch_bounds__(256) void transpose_x(const float* __restrict__ x) {
    __shared__ float t[32][33];
    int b = blockIdx.z;
    int p0 = blockIdx.x * 32, c0 = blockIdx.y * 32;
    int tx = threadIdx.x & 31, ty = threadIdx.x >> 5;
#pragma unroll
    for (int j = 0; j < 4; j++)
        t[ty + 8 * j][tx] = x[((size_t)b * CIN + c0 + ty + 8 * j) * PP + p0 + tx];
    __syncthreads();
#pragma unroll
    for (int j = 0; j < 4; j++) {
        float v = t[tx][ty + 8 * j];
        size_t o = ((size_t)b * PP + p0 + ty + 8 * j) * CIN + c0 + tx;
        g_xT[o] = __float2bfloat16(v);
    }
}

// ---------------- BN apply: Q path -------------------------------------------
__global__ __launch_bounds__(256) void bn_apply_q(void) {
    size_t e = ((size_t)blockIdx.x * 256 + threadIdx.x) * 8;
    int ch = (int)((e >> 11) & (COUT - 1));
    float sc = g_scale[0][ch], sh = g_shift[0][ch];
    uint4 raw = *(uint4*)&g_Yb[e];
    uint32_t rw[4] = {raw.x, raw.y, raw.z, raw.w};
    uint32_t outp[4];
#pragma unroll
    for (int i = 0; i < 4; i++) {
        __nv_bfloat162 pv = *(__nv_bfloat162*)&rw[i];
        float a = __bfloat162float(__low2bfloat16(pv));
        float c = __bfloat162float(__high2bfloat16(pv));
        a = sc * a + sh; a = (a < 0.0f) ? 0.1f * a : a;
        c = sc * c + sh; c = (c < 0.0f) ? 0.1f * c : c;
        outp[i] = cvt_bf16x2(c, a);
    }
    *(uint4*)&g_Q[e] = make_uint4(outp[0], outp[1], outp[2], outp[3]);
}

// ---------------- BN apply + transpose: K/V ----------------------------------
__global__ __launch_bounds__(256) void bn_apply_t(void) {
    __shared__ float t[32][33];
    int z = blockIdx.z;
    int proj = 1 + (z >> 3), b = z & 7;
    int p0 = blockIdx.x * 32, c0 = blockIdx.y * 32;
    int tx = threadIdx.x & 31, ty = threadIdx.x >> 5;
#pragma unroll
    for (int j = 0; j < 4; j++) {
        int c = c0 + ty + 8 * j;
        float sc = g_scale[proj][c], sh = g_shift[proj][c];
        float v = __bfloat162float(
            g_Yb[(((size_t)proj * NB + b) * COUT + c) * PP + p0 + tx]);
        v = sc * v + sh;
        v = (v < 0.0f) ? 0.1f * v : v;
        t[ty + 8 * j][tx] = v;
    }
    __syncthreads();
    bf16* T = (proj == 1) ? g_KT : g_VT;
#pragma unroll
    for (int j = 0; j < 4; j++) {
        float v = t[tx][ty + 8 * j];
        size_t o = ((size_t)b * PP + p0 + ty + 8 * j) * COUT + c0 + tx;
        T[o] = __float2bfloat16(v);
    }
}

// ---------------- launch -----------------------------------------------------
extern "C" void kernel_launch(void* const* d_in, const int* in_sizes, int n_in,
                              void* d_out, int out_size)
{
    (void)in_sizes; (void)n_in; (void)out_size;
    const float* x  = (const float*)d_in[0];
    const float* Wq = (const float*)d_in[1];
    const float* gq = (const float*)d_in[2];
    const float* bq = (const float*)d_in[3];
    const float* Wk = (const float*)d_in[4];
    const float* gk = (const float*)d_in[5];
    const float* bk = (const float*)d_in[6];
    const float* Wv = (const float*)d_in[7];
    const float* gv = (const float*)d_in[8];
    const float* bv = (const float*)d_in[9];
    float* out = (float*)d_out;

    cudaFuncSetAttribute(proj_gemm,  cudaFuncAttributeMaxDynamicSharedMemorySize, SMEM_BYTES);
    cudaFuncSetAttribute(attn_fused, cudaFuncAttributeMaxDynamicSharedMemorySize, SMEM_ATTN);

    // 1) input conversions
    convert_w<<<dim3(COUT * CIN / 4 / 256, 1, 3), 256>>>(Wq, Wk, Wv);
    transpose_x<<<dim3(PP / 32, CIN / 32, NB), 256>>>(x);
    // 2) Y = W x (bf16), fused BN partial stats
    proj_gemm<<<dim3(PP / 128, COUT / 128, 24), 256, SMEM_BYTES>>>();
    // 3) finalize BN stats (cS folded into K)
    stats_reduce<<<3 * COUT, 32>>>(gq, bq, gk, bk, gv, bv);
    // 4) BN + LeakyReLU, emit Q / K^T / V^T single bf16
    bn_apply_q<<<(unsigned)((size_t)NB * COUT * PP / 8 / 256), 256>>>();
    bn_apply_t<<<dim3(PP / 32, COUT / 32, 16), 256>>>();
    // 5) fused attention (R12 known-good: 512 threads, SMEM P, dbuf V/Q)
    attn_fused<<<dim3(16, 64), 512, SMEM_ATTN>>>(out);
}